// round 1
// baseline (speedup 1.0000x reference)
#include <cuda_runtime.h>

// Problem geometry
#define HH   512
#define W4   128          // 512 floats / 4 per float4
#define TSTEPS 198
#define TC   6            // t-chunks
#define TPC  33           // 198 / 6
#define GX   4            // jb blocks: 128/32
#define GY   64           // i  blocks: 512/8
#define NBLK (GX*GY*TC)   // 1536 blocks

// Physics constants (match reference fp32 semantics closely enough for 1e-3)
#define INV_DT   80.0f            // 1/0.0125
#define C_CEN   (-5.0f * 25.0f)   // -5 / DX^2, DX^2 = 0.04 -> *25
#define C_NEAR  ((4.0f/3.0f) * 25.0f)
#define C_FAR   ((-1.0f/12.0f) * 25.0f)
#define MU       0.1f
#define DENOM    52107462.0       // 198 * 513 * 513

__device__ float g_part[NBLK * 2];

__device__ __forceinline__ const float4* frame_ptr(const float4* in4, int t, int ch) {
    return in4 + (size_t)(t * 2 + ch) * (HH * W4);
}

__global__ __launch_bounds__(256, 2)
void pde_mse_kernel(const float* __restrict__ inF) {
    const int tx = threadIdx.x;            // 0..31
    const int ty = threadIdx.y;            // 0..7
    const int jb = blockIdx.x * 32 + tx;   // float4 column block, 0..127
    const int i  = blockIdx.y * 8  + ty;   // row, 0..511
    const int t0 = blockIdx.z * TPC;
    const int t1 = t0 + TPC;

    const float4* __restrict__ in4 = (const float4*)inF;

    const int im1 = (i - 1) & 511, im2 = (i - 2) & 511;
    const int ip1 = (i + 1) & 511, ip2 = (i + 2) & 511;
    const int cl  = (jb - 1) & 127, cr = (jb + 1) & 127;

    // duplicated-edge weights: row 512 == row 0, col 512 == col 0
    const float wi   = (i == 0) ? 2.0f : 1.0f;
    const float w0   = wi * ((jb == 0) ? 2.0f : 1.0f);  // component k==0 holds j==0 when jb==0
    const float wrest = wi;

    float accu = 0.0f, accv = 0.0f;

    // carry t-centers in registers; t+1 load becomes next iteration's center
    float4 uc = frame_ptr(in4, t0, 0)[i * W4 + jb];
    float4 vc = frame_ptr(in4, t0, 1)[i * W4 + jb];

    for (int t = t0; t < t1; ++t) {
        const float4* __restrict__ fu  = frame_ptr(in4, t,     0);
        const float4* __restrict__ fv  = frame_ptr(in4, t,     1);
        const float4* __restrict__ fun = frame_ptr(in4, t + 1, 0);
        const float4* __restrict__ fvn = frame_ptr(in4, t + 1, 1);

        const float4 uL  = fu[i   * W4 + cl];
        const float4 uR  = fu[i   * W4 + cr];
        const float4 uU1 = fu[im1 * W4 + jb];
        const float4 uD1 = fu[ip1 * W4 + jb];
        const float4 uU2 = fu[im2 * W4 + jb];
        const float4 uD2 = fu[ip2 * W4 + jb];

        const float4 vL  = fv[i   * W4 + cl];
        const float4 vR  = fv[i   * W4 + cr];
        const float4 vU1 = fv[im1 * W4 + jb];
        const float4 vD1 = fv[ip1 * W4 + jb];
        const float4 vU2 = fv[im2 * W4 + jb];
        const float4 vD2 = fv[ip2 * W4 + jb];

        const float4 un = fun[i * W4 + jb];
        const float4 vn = fvn[i * W4 + jb];

        const float u[4]   = {uc.x, uc.y, uc.z, uc.w};
        const float v[4]   = {vc.x, vc.y, vc.z, vc.w};
        const float unx[4] = {un.x, un.y, un.z, un.w};
        const float vnx[4] = {vn.x, vn.y, vn.z, vn.w};

        // j-direction neighbor sums (jm1+jp1) and (jm2+jp2) per component
        const float unj[4] = {uL.w + uc.y, uc.x + uc.z, uc.y + uc.w, uc.z + uR.x};
        const float ufj[4] = {uL.z + uc.z, uL.w + uc.w, uc.x + uR.x, uc.y + uR.y};
        const float vnj[4] = {vL.w + vc.y, vc.x + vc.z, vc.y + vc.w, vc.z + vR.x};
        const float vfj[4] = {vL.z + vc.z, vL.w + vc.w, vc.x + vR.x, vc.y + vR.y};

        // i-direction neighbor sums
        const float uni[4] = {uU1.x + uD1.x, uU1.y + uD1.y, uU1.z + uD1.z, uU1.w + uD1.w};
        const float ufi[4] = {uU2.x + uD2.x, uU2.y + uD2.y, uU2.z + uD2.z, uU2.w + uD2.w};
        const float vni[4] = {vU1.x + vD1.x, vU1.y + vD1.y, vU1.z + vD1.z, vU1.w + vD1.w};
        const float vfi[4] = {vU2.x + vD2.x, vU2.y + vD2.y, vU2.z + vD2.z, vU2.w + vD2.w};

        #pragma unroll
        for (int k = 0; k < 4; ++k) {
            const float lap_u = C_CEN * u[k] + C_NEAR * (unj[k] + uni[k]) + C_FAR * (ufj[k] + ufi[k]);
            const float lap_v = C_CEN * v[k] + C_NEAR * (vnj[k] + vni[k]) + C_FAR * (vfj[k] + vfi[k]);

            const float ut = (unx[k] - u[k]) * INV_DT;
            const float vt = (vnx[k] - v[k]) * INV_DT;

            const float s  = u[k] * u[k] + v[k] * v[k];
            const float fu_r = ut - (MU * lap_u + (1.0f - s) * u[k] + s * v[k]);
            const float fv_r = vt - (MU * lap_v + (1.0f - s) * v[k] - s * u[k]);

            const float w = (k == 0) ? w0 : wrest;
            accu += w * fu_r * fu_r;
            accv += w * fv_r * fv_r;
        }

        uc = un;
        vc = vn;
    }

    // warp reduce (warp == one ty row, 32 lanes)
    #pragma unroll
    for (int off = 16; off > 0; off >>= 1) {
        accu += __shfl_down_sync(0xffffffffu, accu, off);
        accv += __shfl_down_sync(0xffffffffu, accv, off);
    }

    __shared__ float su[8], sv[8];
    if (tx == 0) { su[ty] = accu; sv[ty] = accv; }
    __syncthreads();

    if (tx == 0 && ty == 0) {
        float a = 0.0f, b = 0.0f;
        #pragma unroll
        for (int k = 0; k < 8; ++k) { a += su[k]; b += sv[k]; }
        const int bl = (blockIdx.z * GY + blockIdx.y) * GX + blockIdx.x;
        g_part[bl * 2 + 0] = a;
        g_part[bl * 2 + 1] = b;
    }
}

__global__ void finalize_kernel(float* __restrict__ out) {
    __shared__ double sa[256], sb[256];
    double a = 0.0, b = 0.0;
    for (int k = threadIdx.x; k < NBLK; k += 256) {
        a += (double)g_part[2 * k + 0];
        b += (double)g_part[2 * k + 1];
    }
    sa[threadIdx.x] = a;
    sb[threadIdx.x] = b;
    __syncthreads();
    for (int s = 128; s > 0; s >>= 1) {
        if (threadIdx.x < s) {
            sa[threadIdx.x] += sa[threadIdx.x + s];
            sb[threadIdx.x] += sb[threadIdx.x + s];
        }
        __syncthreads();
    }
    if (threadIdx.x == 0) {
        out[0] = (float)(sa[0] / DENOM);
        out[1] = (float)(sb[0] / DENOM);
    }
}

extern "C" void kernel_launch(void* const* d_in, const int* in_sizes, int n_in,
                              void* d_out, int out_size) {
    (void)in_sizes; (void)n_in; (void)out_size;
    const float* in = (const float*)d_in[0];
    float* out = (float*)d_out;

    dim3 grid(GX, GY, TC);
    dim3 block(32, 8);
    pde_mse_kernel<<<grid, block>>>(in);
    finalize_kernel<<<1, 256>>>(out);
}

// round 2
// speedup vs baseline: 1.0562x; 1.0562x over previous
#include <cuda_runtime.h>

// Geometry
#define HH   512
#define W4   128           // 512 floats / 4 per quad
#define TC   6             // t-chunks
#define TPC  33            // 198 / 6
#define GX   4             // 128 quads / 32 lanes
#define GY   32            // 512 rows / (8 warps * 2 rows)
#define NBLK (GX*GY*TC)    // 768

#define DENOM 52107462.0   // 198 * 513 * 513

typedef unsigned long long u64;

__device__ float g_part[NBLK * 2];
__device__ unsigned int g_count = 0;

// ---------- packed f32x2 helpers ----------
__device__ __forceinline__ u64 pk(float a, float b) {
    u64 r; asm("mov.b64 %0, {%1, %2};" : "=l"(r) : "f"(a), "f"(b)); return r;
}
__device__ __forceinline__ void upk(u64 v, float& a, float& b) {
    asm("mov.b64 {%0, %1}, %2;" : "=f"(a), "=f"(b) : "l"(v));
}
__device__ __forceinline__ u64 fadd2(u64 a, u64 b) {
    u64 d; asm("add.rn.f32x2 %0, %1, %2;" : "=l"(d) : "l"(a), "l"(b)); return d;
}
__device__ __forceinline__ u64 fmul2(u64 a, u64 b) {
    u64 d; asm("mul.rn.f32x2 %0, %1, %2;" : "=l"(d) : "l"(a), "l"(b)); return d;
}
__device__ __forceinline__ u64 ffma2(u64 a, u64 b, u64 c) {
    u64 d; asm("fma.rn.f32x2 %0, %1, %2, %3;" : "=l"(d) : "l"(a), "l"(b), "l"(c)); return d;
}

// One channel, one row: laplacian (MU-folded) and (next - cur).
// clo/chi: center quad at t. lhi: left neighbor quad's hi pair. rlo: right's lo pair.
// n1/p1: i-1 / i+1 rows; n2/p2: i-2 / i+2 rows; nx: center at t+1.
__device__ __forceinline__ void lap_d(
    u64 clo, u64 chi, u64 lhi, u64 rlo,
    u64 n1lo, u64 n1hi, u64 p1lo, u64 p1hi,
    u64 n2lo, u64 n2hi, u64 p2lo, u64 p2hi,
    u64 nxlo, u64 nxhi,
    u64 CC, u64 CN, u64 CF, u64 MONE,
    u64& laplo, u64& laphi, u64& dlo, u64& dhi)
{
    float c0, c1, c2, c3, lz, lw, r0, r1;
    upk(clo, c0, c1); upk(chi, c2, c3); upk(lhi, lz, lw); upk(rlo, r0, r1);
    const u64 m1 = pk(lw, c0);
    const u64 m2 = pk(c1, c2);
    const u64 m3 = pk(c3, r0);
    const u64 njlo = fadd2(m1, m2),  njhi = fadd2(m2, m3);
    const u64 fjlo = fadd2(lhi, chi), fjhi = fadd2(clo, rlo);
    const u64 nilo = fadd2(n1lo, p1lo), nihi = fadd2(n1hi, p1hi);
    const u64 filo = fadd2(n2lo, p2lo), fihi = fadd2(n2hi, p2hi);
    const u64 nearlo = fadd2(njlo, nilo), nearhi = fadd2(njhi, nihi);
    const u64 farlo  = fadd2(fjlo, filo), farhi  = fadd2(fjhi, fihi);
    laplo = ffma2(CN, nearlo, ffma2(CF, farlo, fmul2(CC, clo)));
    laphi = ffma2(CN, nearhi, ffma2(CF, farhi, fmul2(CC, chi)));
    dlo = ffma2(clo, MONE, nxlo);   // nx - c
    dhi = ffma2(chi, MONE, nxhi);
}

__global__ __launch_bounds__(256, 2)
void pde_kernel(const float* __restrict__ inF, float* __restrict__ out)
{
    const int tx = threadIdx.x;             // lane
    const int ty = threadIdx.y;             // warp in block
    const int jb = blockIdx.x * 32 + tx;    // quad column 0..127
    const int i0 = (blockIdx.y * 8 + ty) * 2;
    const int t0 = blockIdx.z * TPC;

    const ulonglong2* __restrict__ base = (const ulonglong2*)inF;
    const int FR = HH * W4;                 // 65536 quads per channel-frame
    const size_t FS = (size_t)2 * FR;       // per timestep

    const int im2 = (i0 - 2) & 511, im1 = (i0 - 1) & 511;
    const int ip2 = (i0 + 2) & 511, ip3 = (i0 + 3) & 511;
    const int cl = (jb - 1) & 127, cr = (jb + 1) & 127;

    const int o_m2 = im2 * W4 + jb, o_m1 = im1 * W4 + jb;
    const int o_c0 = i0 * W4 + jb,  o_c1 = (i0 + 1) * W4 + jb;
    const int o_p2 = ip2 * W4 + jb, o_p3 = ip3 * W4 + jb;
    const int o_l0 = i0 * W4 + cl,  o_l1 = (i0 + 1) * W4 + cl;
    const int o_r0 = i0 * W4 + cr,  o_r1 = (i0 + 1) * W4 + cr;

    const ulonglong2* pu = base + (size_t)(t0 * 2 + 0) * FR;
    const ulonglong2* pv = base + (size_t)(t0 * 2 + 1) * FR;

    // MU / DX^2 folded stencil constants
    const float ccf = 0.1f * (-5.0f) * 25.0f;           // -12.5
    const float cnf = 0.1f * (4.0f / 3.0f) * 25.0f;     //  3.3333333
    const float cff = 0.1f * (-1.0f / 12.0f) * 25.0f;   // -0.20833333
    const u64 CC   = pk(ccf, ccf);
    const u64 CN   = pk(cnf, cnf);
    const u64 CF   = pk(cff, cff);
    const u64 MONE = pk(-1.0f, -1.0f);
    const u64 ONE  = pk(1.0f, 1.0f);
    const u64 NIDT = pk(-80.0f, -80.0f);

    // carried centers (rows i0, i0+1) at time t
    ulonglong2 u0 = pu[o_c0], u1 = pu[o_c1];
    ulonglong2 v0 = pv[o_c0], v1 = pv[o_c1];

    // packed accumulators per (row, channel)
    u64 au0l = 0, au0h = 0, au1l = 0, au1h = 0;
    u64 av0l = 0, av0h = 0, av1l = 0, av1h = 0;

    #pragma unroll 1
    for (int it = 0; it < TPC; ++it) {
        const ulonglong2* pun = pu + FS;
        const ulonglong2* pvn = pv + FS;

        // vertical halo rows at t
        const ulonglong2 um2 = pu[o_m2], um1 = pu[o_m1], up2 = pu[o_p2], up3 = pu[o_p3];
        const ulonglong2 vm2 = pv[o_m2], vm1 = pv[o_m1], vp2 = pv[o_p2], vp3 = pv[o_p3];
        // next-t centers
        const ulonglong2 nu0 = pun[o_c0], nu1 = pun[o_c1];
        const ulonglong2 nv0 = pvn[o_c0], nv1 = pvn[o_c1];

        // horizontal neighbors via lane shuffles of carried centers
        u64 u0l = __shfl_up_sync(0xffffffffu, u0.y, 1);
        u64 u1l = __shfl_up_sync(0xffffffffu, u1.y, 1);
        u64 v0l = __shfl_up_sync(0xffffffffu, v0.y, 1);
        u64 v1l = __shfl_up_sync(0xffffffffu, v1.y, 1);
        u64 u0r = __shfl_down_sync(0xffffffffu, u0.x, 1);
        u64 u1r = __shfl_down_sync(0xffffffffu, u1.x, 1);
        u64 v0r = __shfl_down_sync(0xffffffffu, v0.x, 1);
        u64 v1r = __shfl_down_sync(0xffffffffu, v1.x, 1);
        if (tx == 0) {
            u0l = pu[o_l0].y; u1l = pu[o_l1].y;
            v0l = pv[o_l0].y; v1l = pv[o_l1].y;
        }
        if (tx == 31) {
            u0r = pu[o_r0].x; u1r = pu[o_r1].x;
            v0r = pv[o_r0].x; v1r = pv[o_r1].x;
        }

        // ---- row 0 (i0): i-1 = um1, i+1 = u1(carry), i-2 = um2, i+2 = up2
        {
            u64 LUl, LUh, DUl, DUh, LVl, LVh, DVl, DVh;
            lap_d(u0.x, u0.y, u0l, u0r, um1.x, um1.y, u1.x, u1.y,
                  um2.x, um2.y, up2.x, up2.y, nu0.x, nu0.y,
                  CC, CN, CF, MONE, LUl, LUh, DUl, DUh);
            lap_d(v0.x, v0.y, v0l, v0r, vm1.x, vm1.y, v1.x, v1.y,
                  vm2.x, vm2.y, vp2.x, vp2.y, nv0.x, nv0.y,
                  CC, CN, CF, MONE, LVl, LVh, DVl, DVh);

            const u64 sl  = ffma2(u0.x, u0.x, fmul2(v0.x, v0.x));
            const u64 sh  = ffma2(u0.y, u0.y, fmul2(v0.y, v0.y));
            const u64 pl  = ffma2(sl, MONE, ONE);
            const u64 ph  = ffma2(sh, MONE, ONE);
            const u64 nsl = fmul2(sl, MONE);
            const u64 nsh = fmul2(sh, MONE);

            u64 Xul = ffma2(pl, u0.x, ffma2(sl, v0.x, LUl));
            u64 Xuh = ffma2(ph, u0.y, ffma2(sh, v0.y, LUh));
            u64 rul = ffma2(DUl, NIDT, Xul);
            u64 ruh = ffma2(DUh, NIDT, Xuh);
            au0l = ffma2(rul, rul, au0l);
            au0h = ffma2(ruh, ruh, au0h);

            u64 Xvl = ffma2(pl, v0.x, ffma2(nsl, u0.x, LVl));
            u64 Xvh = ffma2(ph, v0.y, ffma2(nsh, u0.y, LVh));
            u64 rvl = ffma2(DVl, NIDT, Xvl);
            u64 rvh = ffma2(DVh, NIDT, Xvh);
            av0l = ffma2(rvl, rvl, av0l);
            av0h = ffma2(rvh, rvh, av0h);
        }

        // ---- row 1 (i0+1): i-1 = u0(carry), i+1 = up2, i-2 = um1, i+2 = up3
        {
            u64 LUl, LUh, DUl, DUh, LVl, LVh, DVl, DVh;
            lap_d(u1.x, u1.y, u1l, u1r, u0.x, u0.y, up2.x, up2.y,
                  um1.x, um1.y, up3.x, up3.y, nu1.x, nu1.y,
                  CC, CN, CF, MONE, LUl, LUh, DUl, DUh);
            lap_d(v1.x, v1.y, v1l, v1r, v0.x, v0.y, vp2.x, vp2.y,
                  vm1.x, vm1.y, vp3.x, vp3.y, nv1.x, nv1.y,
                  CC, CN, CF, MONE, LVl, LVh, DVl, DVh);

            const u64 sl  = ffma2(u1.x, u1.x, fmul2(v1.x, v1.x));
            const u64 sh  = ffma2(u1.y, u1.y, fmul2(v1.y, v1.y));
            const u64 pl  = ffma2(sl, MONE, ONE);
            const u64 ph  = ffma2(sh, MONE, ONE);
            const u64 nsl = fmul2(sl, MONE);
            const u64 nsh = fmul2(sh, MONE);

            u64 Xul = ffma2(pl, u1.x, ffma2(sl, v1.x, LUl));
            u64 Xuh = ffma2(ph, u1.y, ffma2(sh, v1.y, LUh));
            u64 rul = ffma2(DUl, NIDT, Xul);
            u64 ruh = ffma2(DUh, NIDT, Xuh);
            au1l = ffma2(rul, rul, au1l);
            au1h = ffma2(ruh, ruh, au1h);

            u64 Xvl = ffma2(pl, v1.x, ffma2(nsl, u1.x, LVl));
            u64 Xvh = ffma2(ph, v1.y, ffma2(nsh, u1.y, LVh));
            u64 rvl = ffma2(DVl, NIDT, Xvl);
            u64 rvh = ffma2(DVh, NIDT, Xvh);
            av1l = ffma2(rvl, rvl, av1l);
            av1h = ffma2(rvh, rvh, av1h);
        }

        // slide in time: next-t centers become current
        u0 = nu0; u1 = nu1; v0 = nv0; v1 = nv1;
        pu += FS; pv += FS;
    }

    // ---- unpack accumulators and apply duplicated-edge weights ----
    const float wj = (jb == 0) ? 2.0f : 1.0f;   // col 0 duplicated (x of lo pair)
    const float wr = (i0 == 0) ? 2.0f : 1.0f;   // row 0 duplicated (row slot 0)

    float a, b, c, d;
    float sum_u, sum_v;
    upk(au0l, a, b); upk(au0h, c, d);
    sum_u  = wr * (wj * a + b + c + d);
    upk(au1l, a, b); upk(au1h, c, d);
    sum_u += (wj * a + b + c + d);
    upk(av0l, a, b); upk(av0h, c, d);
    sum_v  = wr * (wj * a + b + c + d);
    upk(av1l, a, b); upk(av1h, c, d);
    sum_v += (wj * a + b + c + d);

    // warp reduce
    #pragma unroll
    for (int off = 16; off > 0; off >>= 1) {
        sum_u += __shfl_down_sync(0xffffffffu, sum_u, off);
        sum_v += __shfl_down_sync(0xffffffffu, sum_v, off);
    }

    __shared__ float su[8], sv[8];
    __shared__ bool isLast;
    if (tx == 0) { su[ty] = sum_u; sv[ty] = sum_v; }
    __syncthreads();

    const int tid = ty * 32 + tx;
    if (tid == 0) {
        float pa = 0.0f, pb = 0.0f;
        #pragma unroll
        for (int k = 0; k < 8; ++k) { pa += su[k]; pb += sv[k]; }
        const int blk = (blockIdx.z * GY + blockIdx.y) * GX + blockIdx.x;
        g_part[blk * 2 + 0] = pa;
        g_part[blk * 2 + 1] = pb;
        __threadfence();
        const unsigned int old = atomicAdd(&g_count, 1);
        isLast = (old == (unsigned int)(NBLK - 1));
    }
    __syncthreads();

    // last block folds the partials (deterministic order) — no second launch
    if (isLast) {
        __threadfence();
        double da = 0.0, db = 0.0;
        for (int k = tid; k < NBLK; k += 256) {
            da += (double)g_part[2 * k + 0];
            db += (double)g_part[2 * k + 1];
        }
        __shared__ double sa[256], sb[256];
        sa[tid] = da; sb[tid] = db;
        __syncthreads();
        #pragma unroll
        for (int s = 128; s > 0; s >>= 1) {
            if (tid < s) { sa[tid] += sa[tid + s]; sb[tid] += sb[tid + s]; }
            __syncthreads();
        }
        if (tid == 0) {
            out[0] = (float)(sa[0] / DENOM);
            out[1] = (float)(sb[0] / DENOM);
            g_count = 0;   // reset for next graph replay
        }
    }
}

extern "C" void kernel_launch(void* const* d_in, const int* in_sizes, int n_in,
                              void* d_out, int out_size) {
    (void)in_sizes; (void)n_in; (void)out_size;
    const float* in = (const float*)d_in[0];
    float* out = (float*)d_out;

    dim3 grid(GX, GY, TC);
    dim3 block(32, 8);
    pde_kernel<<<grid, block>>>(in, out);
}